// round 17
// baseline (speedup 1.0000x reference)
#include <cuda_runtime.h>

#define BATCH 8
#define CH    64
#define HH    256
#define WW    256
#define TW    16
#define NT    16                 // tiles along W
#define NCTA  (BATCH * NT)       // 128 CTAs, one wave
#define NTHR  1024               // conv: 64co x 8cig x 2ws ; finalize: 768 = 64co x 12P
#define CIPT  8                  // ci per conv thread
#define NCIG  8
#define KROW  4                  // rows per halo exchange
#define NBLK  63                 // full blocks (rows 1..252); final block = 3 rows
#define NP    12                 // output pairs per row (24-wide region)
#define PSTR  26                 // pp row stride in u64 (25 used)

typedef unsigned long long u64;

union F4U { float4 f; u64 u[2]; };

__device__ int   g_progress[NCTA];
// [slot][cta][side 0=left cols c0..3 / 1=right c12..15][colidx][co]
__device__ float g_halo[2][NCTA][2][KROW][CH];

struct SMEMT {
    u64 pp[2][CH][PSTR];         // duplicated-pair rows, dbl buf   26.6 KB
    u64 red[NP][NCIG][CH];       // partials                        48 KB
};

// ---- packed f32x2 ops ------------------------------------------------------
static __device__ __forceinline__ u64 fma2(u64 a, u64 b, u64 c) {
    u64 d; asm("fma.rn.f32x2 %0, %1, %2, %3;" : "=l"(d) : "l"(a), "l"(b), "l"(c)); return d;
}
static __device__ __forceinline__ u64 add2(u64 a, u64 b) {
    u64 d; asm("add.rn.f32x2 %0, %1, %2;" : "=l"(d) : "l"(a), "l"(b)); return d;
}
static __device__ __forceinline__ u64 splat2(float x) {
    u64 r; asm("mov.b64 %0, {%1, %1};" : "=l"(r) : "f"(x)); return r;
}
static __device__ __forceinline__ void unpack2(u64 v, float& lo, float& hi) {
    unsigned a, b;
    asm("mov.b64 {%0,%1}, %2;" : "=r"(a), "=r"(b) : "l"(v));
    lo = __uint_as_float(a); hi = __uint_as_float(b);
}
static __device__ __forceinline__ float ftanh(float x) {
    float e = __expf(2.0f * x);
    return 1.0f - __fdividef(2.0f, e + 1.0f);
}
static __device__ __forceinline__ int ld_acq(const int* p) {
    int v;
    asm volatile("ld.acquire.gpu.global.b32 %0, [%1];" : "=r"(v) : "l"(p));
    return v;
}
static __device__ __forceinline__ void st_rel(int* p, int v) {
    asm volatile("st.release.gpu.global.b32 [%0], %1;" :: "l"(p), "r"(v) : "memory");
}

__global__ void reset_kernel() {
    if (threadIdx.x < NCTA) g_progress[threadIdx.x] = -1;
}

__global__ void __launch_bounds__(NTHR, 1)
spatial_kernel(const float* __restrict__ X, const float* __restrict__ Wc,
               const float* __restrict__ bc, float* __restrict__ out) {
    extern __shared__ char smraw[];
    SMEMT* sm = reinterpret_cast<SMEMT*>(smraw);

    const int tid = threadIdx.x;
    const int co  = tid & 63;            // channel (conv + finalize)
    const int cig = (tid >> 6) & 7;      // ci-group (conv)
    const int ws  = tid >> 9;            // 0: pairs 0..5, 1: pairs 6..11
    const int bid = blockIdx.x;
    const int b   = bid >> 4;
    const int t   = bid & 15;
    const int w0  = t * TW;

    // finalize identity (tid < 768): pair P of channel co
    const int  P    = tid >> 6;              // 0..11 when fin
    const bool fin  = (tid < 768);
    const int  c0   = 2 * P - 4;             // output cols c0, c0+1  (-4..19)
    const bool mask = (t == 0 && P < 2) || (t == NT - 1 && P >= 10);
    const bool own  = (P >= 2 && P <= 9);    // owned cols 0..15

    // ---- weights: 8 ci x 3 taps ----
    float wr[CIPT * 3];
    {
        const float4* wp = reinterpret_cast<const float4*>(
            Wc + ((size_t)co * CH + cig * CIPT) * 3);
#pragma unroll
        for (int i = 0; i < 6; i++) {
            float4 v = wp[i];
            wr[i * 4 + 0] = v.x; wr[i * 4 + 1] = v.y;
            wr[i * 4 + 2] = v.z; wr[i * 4 + 3] = v.w;
        }
    }
    const float bias = bc[co];

    if (tid < CH) {   // fq[0] and fq[49] stay 0 forever
        float* f0 = reinterpret_cast<float*>(&sm->pp[0][tid][0]);
        float* f1 = reinterpret_cast<float*>(&sm->pp[1][tid][0]);
        f0[0] = 0.f; f1[0] = 0.f; f0[49] = 0.f; f1[49] = 0.f;
    }
    __syncthreads();

    const size_t chbase = ((size_t)(b * CH + co) * HH) * WW + w0;

    // ---- row 0: Y[0] = X[0] over full 24-wide region (finalize threads) ----
    if (fin) {
        float2 x2 = make_float2(0.f, 0.f);
        if (!mask) x2 = *reinterpret_cast<const float2*>(X + chbase + c0);
        float* fq = reinterpret_cast<float*>(&sm->pp[0][co][0]);
        fq[4*P+1] = x2.x; fq[4*P+2] = x2.x; fq[4*P+3] = x2.y; fq[4*P+4] = x2.y;
        if (own) *reinterpret_cast<float2*>(out + chbase + c0) = x2;
        if (P == 2 || P == 3) {
            g_halo[0][bid][0][c0][co] = x2.x;   g_halo[0][bid][0][c0+1][co] = x2.y;
        }
        if (P == 8 || P == 9) {
            g_halo[0][bid][1][c0-12][co] = x2.x; g_halo[0][bid][1][c0-11][co] = x2.y;
        }
    }
    __syncthreads();
    if (tid == 0) st_rel(&g_progress[bid], 0);

    int cur = 0;
    for (int blk = 0; blk <= NBLK; blk++) {
        const int slot = blk & 1;

        // ---- handshake: wait neighbors' base row (2 pollsters) ----
        if (tid == 0 && t > 0)
            while (ld_acq(&g_progress[bid - 1]) < blk) { }
        if (tid == 512 && t < NT - 1)
            while (ld_acq(&g_progress[bid + 1]) < blk) { }
        __syncthreads();   // S1

        // ---- patch base-row halo columns in pp[cur] ----
        if (tid < 64) {
            if (t > 0) {   // left: neighbor's c12..15 -> my u0..3
                float* fq = reinterpret_cast<float*>(&sm->pp[cur][tid][0]);
#pragma unroll
                for (int j = 0; j < KROW; j++) {
                    float v = g_halo[slot][bid - 1][1][j][tid];
                    fq[1 + 2*j] = v; fq[2 + 2*j] = v;
                }
            }
        } else if (tid < 128) {
            if (t < NT - 1) {   // right: neighbor's c0..3 -> my u20..23
                float* fq = reinterpret_cast<float*>(&sm->pp[cur][tid - 64][0]);
#pragma unroll
                for (int j = 0; j < KROW; j++) {
                    float v = g_halo[slot][bid + 1][0][j][tid - 64];
                    fq[41 + 2*j] = v; fq[42 + 2*j] = v;
                }
            }
        }
        __syncthreads();   // S1b: base row complete

        const int  jmax    = (blk == NBLK) ? 3 : KROW;
        const bool publish = (blk < NBLK);

        for (int j = 1; j <= jmax; j++) {
            const int r = blk * KROW + j;
            const size_t rbase = chbase + (size_t)r * WW;

            // X prefetch (finalize threads, consumed post-S2)
            float2 x2 = make_float2(0.f, 0.f);
            if (fin && !mask) x2 = *reinterpret_cast<const float2*>(X + rbase + c0);

            // ---- conv: 8 ci x 6 pairs (this thread's half) ----
            u64 s0 = 0ull, s1 = 0ull, s2 = 0ull, s3 = 0ull, s4 = 0ull, s5 = 0ull;
            {
                // ws=0: u64 idx 0..12 ; ws=1: idx 12..24
                const u64* rowb = &sm->pp[cur][cig * CIPT][0];
                const int  base4 = ws * 6;       // q4 index base
                const int  tailidx = 12 + ws * 12;
#pragma unroll
                for (int jc = 0; jc < CIPT; jc++) {
                    const u64* q = rowb + jc * PSTR;
                    const float4* q4 = reinterpret_cast<const float4*>(q) + base4;
                    F4U a0, a1, a2, a3, a4, a5;
                    a0.f = q4[0]; a1.f = q4[1]; a2.f = q4[2];
                    a3.f = q4[3]; a4.f = q4[4]; a5.f = q4[5];
                    u64 tail = q[tailidx];
                    u64 k0 = splat2(wr[jc * 3 + 0]);
                    u64 k1 = splat2(wr[jc * 3 + 1]);
                    u64 k2 = splat2(wr[jc * 3 + 2]);
                    s0 = fma2(k0, a0.u[0], s0); s0 = fma2(k1, a0.u[1], s0); s0 = fma2(k2, a1.u[0], s0);
                    s1 = fma2(k0, a1.u[0], s1); s1 = fma2(k1, a1.u[1], s1); s1 = fma2(k2, a2.u[0], s1);
                    s2 = fma2(k0, a2.u[0], s2); s2 = fma2(k1, a2.u[1], s2); s2 = fma2(k2, a3.u[0], s2);
                    s3 = fma2(k0, a3.u[0], s3); s3 = fma2(k1, a3.u[1], s3); s3 = fma2(k2, a4.u[0], s3);
                    s4 = fma2(k0, a4.u[0], s4); s4 = fma2(k1, a4.u[1], s4); s4 = fma2(k2, a5.u[0], s4);
                    s5 = fma2(k0, a5.u[0], s5); s5 = fma2(k1, a5.u[1], s5); s5 = fma2(k2, tail,    s5);
                }
            }
            {
                const int pb = ws * 6;
                sm->red[pb + 0][cig][co] = s0;
                sm->red[pb + 1][cig][co] = s1;
                sm->red[pb + 2][cig][co] = s2;
                sm->red[pb + 3][cig][co] = s3;
                sm->red[pb + 4][cig][co] = s4;
                sm->red[pb + 5][cig][co] = s5;
            }
            __syncthreads();   // S2: partials visible

            // ---- finalize: reduce 8 cigs, activate, publish (768 threads) ----
            if (fin) {
                u64 acc = sm->red[P][0][co];
#pragma unroll
                for (int c = 1; c < NCIG; c++) acc = add2(acc, sm->red[P][c][co]);
                float slo, shi; unpack2(acc, slo, shi);
                float y0 = x2.x + ftanh(slo + bias);
                float y1 = x2.y + ftanh(shi + bias);
                if (mask) { y0 = 0.f; y1 = 0.f; }
                float* fq = reinterpret_cast<float*>(&sm->pp[cur ^ 1][co][0]);
                fq[4*P+1] = y0; fq[4*P+2] = y0; fq[4*P+3] = y1; fq[4*P+4] = y1;
                if (own) *reinterpret_cast<float2*>(out + rbase + c0) = make_float2(y0, y1);
                if (publish && j == KROW) {
                    if (P == 2 || P == 3) {
                        g_halo[slot ^ 1][bid][0][c0][co]   = y0;
                        g_halo[slot ^ 1][bid][0][c0+1][co] = y1;
                    }
                    if (P == 8 || P == 9) {
                        g_halo[slot ^ 1][bid][1][c0-12][co] = y0;
                        g_halo[slot ^ 1][bid][1][c0-11][co] = y1;
                    }
                }
            }
            __syncthreads();   // S3: pp[nxt] + halo stores done
            cur ^= 1;
        }

        if (tid == 0 && publish) st_rel(&g_progress[bid], blk + 1);
    }
}

extern "C" void kernel_launch(void* const* d_in, const int* in_sizes, int n_in,
                              void* d_out, int out_size) {
    const float* X  = (const float*)d_in[0];
    const float* Wc = (const float*)d_in[1];
    const float* bc = (const float*)d_in[2];
    float* out = (float*)d_out;

    cudaFuncSetAttribute(spatial_kernel,
                         cudaFuncAttributeMaxDynamicSharedMemorySize,
                         (int)sizeof(SMEMT));

    reset_kernel<<<1, NCTA>>>();
    spatial_kernel<<<NCTA, NTHR, sizeof(SMEMT)>>>(X, Wc, bc, out);
}